// round 2
// baseline (speedup 1.0000x reference)
#include <cuda_runtime.h>
#include <cuda_bf16.h>
#include <cstdint>
#include <math.h>

#define N_TOK 2048
#define C_DIM 768
#define E_NUM 32
#define H_DIM 3072

#define BM 128
#define BN 128
#define BK 32
#define APAD 8
#define BPAD 8
#define ASTRIDE (BK + APAD)    // 40
#define BSTRIDE (BN + BPAD)    // 136

// ---------------- scratch (device globals; no allocations allowed) ----------
__device__ float g_gates[N_TOK * E_NUM];                         // 256 KB
__device__ float g_h[(size_t)E_NUM * N_TOK * H_DIM];             // 805 MB
__device__ float g_part[4 * N_TOK * C_DIM];                      // 25 MB

// ---------------- helpers ---------------------------------------------------
__device__ __forceinline__ uint32_t smem_u32(const void* p) {
    return (uint32_t)__cvta_generic_to_shared(p);
}

__device__ __forceinline__ void ldm_x4(uint32_t r[4], uint32_t addr) {
    asm volatile("ldmatrix.sync.aligned.m8n8.x4.shared.b16 {%0,%1,%2,%3}, [%4];"
                 : "=r"(r[0]), "=r"(r[1]), "=r"(r[2]), "=r"(r[3]) : "r"(addr));
}
__device__ __forceinline__ void ldm_x4_t(uint32_t r[4], uint32_t addr) {
    asm volatile("ldmatrix.sync.aligned.m8n8.x4.trans.shared.b16 {%0,%1,%2,%3}, [%4];"
                 : "=r"(r[0]), "=r"(r[1]), "=r"(r[2]), "=r"(r[3]) : "r"(addr));
}
__device__ __forceinline__ void mma16816(float d[4], const uint32_t a[4], const uint32_t b[2]) {
    asm volatile("mma.sync.aligned.m16n8k16.row.col.f32.bf16.bf16.f32 "
                 "{%0,%1,%2,%3},{%4,%5,%6,%7},{%8,%9},{%0,%1,%2,%3};"
                 : "+f"(d[0]), "+f"(d[1]), "+f"(d[2]), "+f"(d[3])
                 : "r"(a[0]), "r"(a[1]), "r"(a[2]), "r"(a[3]), "r"(b[0]), "r"(b[1]));
}

// split a float4 into hi/lo bf16 and store 4 consecutive elements to SMEM
__device__ __forceinline__ void split_store(__nv_bfloat16* hi, __nv_bfloat16* lo, float4 v) {
    float f[4] = {v.x, v.y, v.z, v.w};
    __nv_bfloat16 h[4], l[4];
#pragma unroll
    for (int q = 0; q < 4; q++) {
        h[q] = __float2bfloat16(f[q]);
        l[q] = __float2bfloat16(f[q] - __bfloat162float(h[q]));
    }
    *reinterpret_cast<__nv_bfloat162*>(hi)     = __halves2bfloat162(h[0], h[1]);
    *reinterpret_cast<__nv_bfloat162*>(hi + 2) = __halves2bfloat162(h[2], h[3]);
    *reinterpret_cast<__nv_bfloat162*>(lo)     = __halves2bfloat162(l[0], l[1]);
    *reinterpret_cast<__nv_bfloat162*>(lo + 2) = __halves2bfloat162(l[2], l[3]);
}

__device__ __forceinline__ float gelu_f(float v) {
    return 0.5f * v * (1.0f + erff(v * 0.70710678118654752f));
}

// One BK-wide stage of the 3-pass (hi*hi + hi*lo + lo*hi) 128x128 MMA tile.
// 8 warps arranged 4(M) x 2(N); per warp: M 32 x N 64.
__device__ __forceinline__ void mma_stage(
    const __nv_bfloat16* As_hi, const __nv_bfloat16* As_lo,
    const __nv_bfloat16* Bs_hi, const __nv_bfloat16* Bs_lo,
    int lane, int wm, int wn, float acc[2][8][4])
{
#pragma unroll
    for (int kk = 0; kk < 2; kk++) {
        uint32_t ah[2][4], al[2][4];
#pragma unroll
        for (int mi = 0; mi < 2; mi++) {
            int off = (wm * 32 + mi * 16 + (lane & 15)) * ASTRIDE + kk * 16 + ((lane >> 4) << 3);
            ldm_x4(ah[mi], smem_u32(As_hi + off));
            ldm_x4(al[mi], smem_u32(As_lo + off));
        }
        uint32_t bh[4][4], bl[4][4];
#pragma unroll
        for (int nj = 0; nj < 4; nj++) {
            int off = (kk * 16 + (lane & 15)) * BSTRIDE + wn * 64 + nj * 16 + ((lane >> 4) << 3);
            ldm_x4_t(bh[nj], smem_u32(Bs_hi + off));
            ldm_x4_t(bl[nj], smem_u32(Bs_lo + off));
        }
#pragma unroll
        for (int mi = 0; mi < 2; mi++) {
#pragma unroll
            for (int n8 = 0; n8 < 8; n8++) {
                const uint32_t* Bh = &bh[n8 >> 1][(n8 & 1) * 2];
                const uint32_t* Bl = &bl[n8 >> 1][(n8 & 1) * 2];
                mma16816(acc[mi][n8], ah[mi], Bh);  // hi*hi
                mma16816(acc[mi][n8], ah[mi], Bl);  // hi*lo
                mma16816(acc[mi][n8], al[mi], Bh);  // lo*hi
            }
        }
    }
}

// ---------------- kernel 1: gating softmax ----------------------------------
__global__ void gate_kernel(const float* __restrict__ x,
                            const float* __restrict__ gw,
                            const float* __restrict__ gb)
{
    int token = (blockIdx.x * blockDim.x + threadIdx.x) >> 5;
    int lane = threadIdx.x & 31;
    if (token >= N_TOK) return;
    const float* xr = x + (size_t)token * C_DIM;
    float acc = gb[lane];
#pragma unroll 4
    for (int k = 0; k < C_DIM; k++)
        acc = fmaf(xr[k], gw[k * E_NUM + lane], acc);
    float mx = acc;
#pragma unroll
    for (int o = 16; o > 0; o >>= 1) mx = fmaxf(mx, __shfl_xor_sync(0xffffffffu, mx, o));
    float ev = expf(acc - mx);
    float sm = ev;
#pragma unroll
    for (int o = 16; o > 0; o >>= 1) sm += __shfl_xor_sync(0xffffffffu, sm, o);
    g_gates[token * E_NUM + lane] = ev / sm;
}

// ---------------- kernel 2: FFN1  h = gelu(x @ w1[e] + b1[e]) ---------------
__global__ __launch_bounds__(256) void ffn1_kernel(
    const float* __restrict__ x, const float* __restrict__ w1, const float* __restrict__ b1)
{
    __shared__ __nv_bfloat16 As_hi[BM * ASTRIDE], As_lo[BM * ASTRIDE];
    __shared__ __nv_bfloat16 Bs_hi[BK * BSTRIDE], Bs_lo[BK * BSTRIDE];

    const int m0 = blockIdx.x * BM;
    const int h0 = blockIdx.y * BN;
    const int e  = blockIdx.z;
    const float* w1e = w1 + (size_t)e * C_DIM * H_DIM;

    const int t = threadIdx.x, lane = t & 31, wid = t >> 5;
    const int wm = wid & 3, wn = wid >> 2;

    float acc[2][8][4];
#pragma unroll
    for (int mi = 0; mi < 2; mi++)
#pragma unroll
        for (int n8 = 0; n8 < 8; n8++)
#pragma unroll
            for (int q = 0; q < 4; q++) acc[mi][n8][q] = 0.0f;

    float4 ra[4], rb[4];
    auto loadG = [&](int k0) {
#pragma unroll
        for (int j = 0; j < 4; j++) {
            int i = t + 256 * j;
            ra[j] = *reinterpret_cast<const float4*>(
                x + (size_t)(m0 + (i >> 3)) * C_DIM + k0 + (i & 7) * 4);
            rb[j] = *reinterpret_cast<const float4*>(
                w1e + (size_t)(k0 + (i >> 5)) * H_DIM + h0 + (i & 31) * 4);
        }
    };
    auto storeS = [&]() {
#pragma unroll
        for (int j = 0; j < 4; j++) {
            int i = t + 256 * j;
            split_store(&As_hi[(i >> 3) * ASTRIDE + (i & 7) * 4],
                        &As_lo[(i >> 3) * ASTRIDE + (i & 7) * 4], ra[j]);
            split_store(&Bs_hi[(i >> 5) * BSTRIDE + (i & 31) * 4],
                        &Bs_lo[(i >> 5) * BSTRIDE + (i & 31) * 4], rb[j]);
        }
    };

    const int NSTAGE = C_DIM / BK;  // 24
    loadG(0);
    storeS();
    __syncthreads();
    for (int s = 0; s < NSTAGE; s++) {
        if (s + 1 < NSTAGE) loadG((s + 1) * BK);
        mma_stage(As_hi, As_lo, Bs_hi, Bs_lo, lane, wm, wn, acc);
        __syncthreads();
        if (s + 1 < NSTAGE) { storeS(); __syncthreads(); }
    }

    // epilogue: + b1, exact gelu, store fp32 h
    const int gid = lane >> 2, tg = lane & 3;
#pragma unroll
    for (int mi = 0; mi < 2; mi++) {
#pragma unroll
        for (int n8 = 0; n8 < 8; n8++) {
            int m = m0 + wm * 32 + mi * 16 + gid;
            int hc = h0 + wn * 64 + n8 * 8 + tg * 2;
            float bz0 = b1[e * H_DIM + hc];
            float bz1 = b1[e * H_DIM + hc + 1];
            float* a = acc[mi][n8];
            float2 v0 = {gelu_f(a[0] + bz0), gelu_f(a[1] + bz1)};
            float2 v1 = {gelu_f(a[2] + bz0), gelu_f(a[3] + bz1)};
            size_t base = ((size_t)e * N_TOK + m) * H_DIM + hc;
            *reinterpret_cast<float2*>(&g_h[base]) = v0;
            *reinterpret_cast<float2*>(&g_h[base + (size_t)8 * H_DIM]) = v1;
        }
    }
}

// ---------------- kernel 3: FFN2  part[g] = sum_{e in g} gate_e*(h_e @ w2_e) -
__global__ __launch_bounds__(256) void ffn2_kernel(const float* __restrict__ w2)
{
    __shared__ __nv_bfloat16 As_hi[BM * ASTRIDE], As_lo[BM * ASTRIDE];
    __shared__ __nv_bfloat16 Bs_hi[BK * BSTRIDE], Bs_lo[BK * BSTRIDE];

    const int m0 = blockIdx.x * BM;
    const int c0 = blockIdx.y * BN;
    const int grp = blockIdx.z;                  // 4 groups of 8 experts
    const int t = threadIdx.x, lane = t & 31, wid = t >> 5;
    const int wm = wid & 3, wn = wid >> 2;

    float acc[2][8][4];
#pragma unroll
    for (int mi = 0; mi < 2; mi++)
#pragma unroll
        for (int n8 = 0; n8 < 8; n8++)
#pragma unroll
            for (int q = 0; q < 4; q++) acc[mi][n8][q] = 0.0f;

    const int KST = H_DIM / BK;      // 96 stages per expert
    const int NSTAGE = 8 * KST;      // 768 total

    float4 ra[4], rb[4];
    auto loadG = [&](int s) {
        int e = grp * 8 + s / KST;
        int k0 = (s % KST) * BK;
        const float* w2e = w2 + (size_t)e * H_DIM * C_DIM;
#pragma unroll
        for (int j = 0; j < 4; j++) {
            int i = t + 256 * j;
            int row = i >> 3;
            float g = g_gates[(m0 + row) * E_NUM + e];
            float4 v = *reinterpret_cast<const float4*>(
                &g_h[((size_t)e * N_TOK + m0 + row) * H_DIM + k0 + (i & 7) * 4]);
            v.x *= g; v.y *= g; v.z *= g; v.w *= g;   // fold gate into A, then re-split
            ra[j] = v;
            rb[j] = *reinterpret_cast<const float4*>(
                w2e + (size_t)(k0 + (i >> 5)) * C_DIM + c0 + (i & 31) * 4);
        }
    };
    auto storeS = [&]() {
#pragma unroll
        for (int j = 0; j < 4; j++) {
            int i = t + 256 * j;
            split_store(&As_hi[(i >> 3) * ASTRIDE + (i & 7) * 4],
                        &As_lo[(i >> 3) * ASTRIDE + (i & 7) * 4], ra[j]);
            split_store(&Bs_hi[(i >> 5) * BSTRIDE + (i & 31) * 4],
                        &Bs_lo[(i >> 5) * BSTRIDE + (i & 31) * 4], rb[j]);
        }
    };

    loadG(0);
    storeS();
    __syncthreads();
    for (int s = 0; s < NSTAGE; s++) {
        if (s + 1 < NSTAGE) loadG(s + 1);
        mma_stage(As_hi, As_lo, Bs_hi, Bs_lo, lane, wm, wn, acc);
        __syncthreads();
        if (s + 1 < NSTAGE) { storeS(); __syncthreads(); }
    }

    const int gid = lane >> 2, tg = lane & 3;
#pragma unroll
    for (int mi = 0; mi < 2; mi++) {
#pragma unroll
        for (int n8 = 0; n8 < 8; n8++) {
            int m = m0 + wm * 32 + mi * 16 + gid;
            int cc = c0 + wn * 64 + n8 * 8 + tg * 2;
            float* a = acc[mi][n8];
            size_t base = ((size_t)grp * N_TOK + m) * C_DIM + cc;
            *reinterpret_cast<float2*>(&g_part[base]) = make_float2(a[0], a[1]);
            *reinterpret_cast<float2*>(&g_part[base + (size_t)8 * C_DIM]) = make_float2(a[2], a[3]);
        }
    }
}

// ---------------- kernel 4: finalize  out = sum_g part + sum_e gate*b2 ------
__global__ void finalize_kernel(const float* __restrict__ b2, float* __restrict__ out)
{
    int i = blockIdx.x * 256 + threadIdx.x;
    if (i >= N_TOK * C_DIM) return;
    int m = i / C_DIM, c = i % C_DIM;
    float s = g_part[i]
            + g_part[N_TOK * C_DIM + i]
            + g_part[2 * N_TOK * C_DIM + i]
            + g_part[3 * N_TOK * C_DIM + i];
    const float* gr = &g_gates[m * E_NUM];
#pragma unroll
    for (int e = 0; e < E_NUM; e++)
        s += gr[e] * b2[e * C_DIM + c];
    out[i] = s;
}

// ---------------- launch -----------------------------------------------------
extern "C" void kernel_launch(void* const* d_in, const int* in_sizes, int n_in,
                              void* d_out, int out_size)
{
    (void)in_sizes; (void)n_in; (void)out_size;
    const float* x      = (const float*)d_in[0];
    const float* gate_w = (const float*)d_in[1];
    const float* gate_b = (const float*)d_in[2];
    const float* w1     = (const float*)d_in[3];
    const float* b1     = (const float*)d_in[4];
    const float* w2     = (const float*)d_in[5];
    const float* b2     = (const float*)d_in[6];
    float* out = (float*)d_out;

    gate_kernel<<<N_TOK / 8, 256>>>(x, gate_w, gate_b);
    ffn1_kernel<<<dim3(N_TOK / BM, H_DIM / BN, E_NUM), 256>>>(x, w1, b1);
    ffn2_kernel<<<dim3(N_TOK / BM, C_DIM / BN, 4), 256>>>(w2);
    finalize_kernel<<<(N_TOK * C_DIM + 255) / 256, 256>>>(b2, out);
}

// round 3
// speedup vs baseline: 1.4998x; 1.4998x over previous
#include <cuda_runtime.h>
#include <cuda_bf16.h>
#include <cstdint>
#include <math.h>

#define N_TOK 2048
#define C_DIM 768
#define E_NUM 32
#define H_DIM 3072

#define BM 128
#define BN 128
#define BK 32
#define APAD 8
#define BPAD 8
#define ASTRIDE (BK + APAD)    // 40
#define BSTRIDE (BN + BPAD)    // 136

// ---------------- scratch (device globals; no allocations allowed) ----------
__device__ float g_gates[N_TOK * E_NUM];                         // 256 KB
__device__ float g_h[(size_t)E_NUM * N_TOK * H_DIM];             // 805 MB
__device__ float g_part[4 * N_TOK * C_DIM];                      // 25 MB

// ---------------- helpers ---------------------------------------------------
__device__ __forceinline__ uint32_t smem_u32(const void* p) {
    return (uint32_t)__cvta_generic_to_shared(p);
}

__device__ __forceinline__ void ldm_x4(uint32_t r[4], uint32_t addr) {
    asm volatile("ldmatrix.sync.aligned.m8n8.x4.shared.b16 {%0,%1,%2,%3}, [%4];"
                 : "=r"(r[0]), "=r"(r[1]), "=r"(r[2]), "=r"(r[3]) : "r"(addr));
}
__device__ __forceinline__ void ldm_x4_t(uint32_t r[4], uint32_t addr) {
    asm volatile("ldmatrix.sync.aligned.m8n8.x4.trans.shared.b16 {%0,%1,%2,%3}, [%4];"
                 : "=r"(r[0]), "=r"(r[1]), "=r"(r[2]), "=r"(r[3]) : "r"(addr));
}
__device__ __forceinline__ void mma16816(float d[4], const uint32_t a[4], const uint32_t b[2]) {
    asm volatile("mma.sync.aligned.m16n8k16.row.col.f32.bf16.bf16.f32 "
                 "{%0,%1,%2,%3},{%4,%5,%6,%7},{%8,%9},{%0,%1,%2,%3};"
                 : "+f"(d[0]), "+f"(d[1]), "+f"(d[2]), "+f"(d[3])
                 : "r"(a[0]), "r"(a[1]), "r"(a[2]), "r"(a[3]), "r"(b[0]), "r"(b[1]));
}

// split a float4 into hi/lo bf16 and store 4 consecutive elements to SMEM
__device__ __forceinline__ void split_store(__nv_bfloat16* hi, __nv_bfloat16* lo, float4 v) {
    float f[4] = {v.x, v.y, v.z, v.w};
    __nv_bfloat16 h[4], l[4];
#pragma unroll
    for (int q = 0; q < 4; q++) {
        h[q] = __float2bfloat16(f[q]);
        l[q] = __float2bfloat16(f[q] - __bfloat162float(h[q]));
    }
    *reinterpret_cast<__nv_bfloat162*>(hi)     = __halves2bfloat162(h[0], h[1]);
    *reinterpret_cast<__nv_bfloat162*>(hi + 2) = __halves2bfloat162(h[2], h[3]);
    *reinterpret_cast<__nv_bfloat162*>(lo)     = __halves2bfloat162(l[0], l[1]);
    *reinterpret_cast<__nv_bfloat162*>(lo + 2) = __halves2bfloat162(l[2], l[3]);
}

__device__ __forceinline__ float gelu_f(float v) {
    return 0.5f * v * (1.0f + erff(v * 0.70710678118654752f));
}

// One BK-wide stage of the 3-pass (hi*hi + hi*lo + lo*hi) 128x128 MMA tile.
// 8 warps arranged 4(M) x 2(N); per warp: M 32 x N 64.
__device__ __forceinline__ void mma_stage(
    const __nv_bfloat16* As_hi, const __nv_bfloat16* As_lo,
    const __nv_bfloat16* Bs_hi, const __nv_bfloat16* Bs_lo,
    int lane, int wm, int wn, float acc[2][8][4])
{
#pragma unroll
    for (int kk = 0; kk < 2; kk++) {
        uint32_t ah[2][4], al[2][4];
#pragma unroll
        for (int mi = 0; mi < 2; mi++) {
            int off = (wm * 32 + mi * 16 + (lane & 15)) * ASTRIDE + kk * 16 + ((lane >> 4) << 3);
            ldm_x4(ah[mi], smem_u32(As_hi + off));
            ldm_x4(al[mi], smem_u32(As_lo + off));
        }
        uint32_t bh[4][4], bl[4][4];
#pragma unroll
        for (int nj = 0; nj < 4; nj++) {
            int off = (kk * 16 + (lane & 15)) * BSTRIDE + wn * 64 + nj * 16 + ((lane >> 4) << 3);
            ldm_x4_t(bh[nj], smem_u32(Bs_hi + off));
            ldm_x4_t(bl[nj], smem_u32(Bs_lo + off));
        }
#pragma unroll
        for (int mi = 0; mi < 2; mi++) {
#pragma unroll
            for (int n8 = 0; n8 < 8; n8++) {
                const uint32_t* Bh = &bh[n8 >> 1][(n8 & 1) * 2];
                const uint32_t* Bl = &bl[n8 >> 1][(n8 & 1) * 2];
                mma16816(acc[mi][n8], ah[mi], Bh);  // hi*hi
                mma16816(acc[mi][n8], ah[mi], Bl);  // hi*lo
                mma16816(acc[mi][n8], al[mi], Bh);  // lo*hi
            }
        }
    }
}

// ---------------- kernel 1: gating softmax ----------------------------------
__global__ void gate_kernel(const float* __restrict__ x,
                            const float* __restrict__ gw,
                            const float* __restrict__ gb)
{
    int token = (blockIdx.x * blockDim.x + threadIdx.x) >> 5;
    int lane = threadIdx.x & 31;
    if (token >= N_TOK) return;
    const float* xr = x + (size_t)token * C_DIM;
    float acc = gb[lane];
#pragma unroll 4
    for (int k = 0; k < C_DIM; k++)
        acc = fmaf(xr[k], gw[k * E_NUM + lane], acc);
    float mx = acc;
#pragma unroll
    for (int o = 16; o > 0; o >>= 1) mx = fmaxf(mx, __shfl_xor_sync(0xffffffffu, mx, o));
    float ev = expf(acc - mx);
    float sm = ev;
#pragma unroll
    for (int o = 16; o > 0; o >>= 1) sm += __shfl_xor_sync(0xffffffffu, sm, o);
    g_gates[token * E_NUM + lane] = ev / sm;
}

// ---------------- kernel 2: FFN1  h = gelu(x @ w1[e] + b1[e]) ---------------
__global__ __launch_bounds__(256) void ffn1_kernel(
    const float* __restrict__ x, const float* __restrict__ w1, const float* __restrict__ b1)
{
    __shared__ __nv_bfloat16 As_hi[BM * ASTRIDE], As_lo[BM * ASTRIDE];
    __shared__ __nv_bfloat16 Bs_hi[BK * BSTRIDE], Bs_lo[BK * BSTRIDE];

    const int m0 = blockIdx.x * BM;
    const int h0 = blockIdx.y * BN;
    const int e  = blockIdx.z;
    const float* w1e = w1 + (size_t)e * C_DIM * H_DIM;

    const int t = threadIdx.x, lane = t & 31, wid = t >> 5;
    const int wm = wid & 3, wn = wid >> 2;

    float acc[2][8][4];
#pragma unroll
    for (int mi = 0; mi < 2; mi++)
#pragma unroll
        for (int n8 = 0; n8 < 8; n8++)
#pragma unroll
            for (int q = 0; q < 4; q++) acc[mi][n8][q] = 0.0f;

    float4 ra[4], rb[4];
    auto loadG = [&](int k0) {
#pragma unroll
        for (int j = 0; j < 4; j++) {
            int i = t + 256 * j;
            ra[j] = *reinterpret_cast<const float4*>(
                x + (size_t)(m0 + (i >> 3)) * C_DIM + k0 + (i & 7) * 4);
            rb[j] = *reinterpret_cast<const float4*>(
                w1e + (size_t)(k0 + (i >> 5)) * H_DIM + h0 + (i & 31) * 4);
        }
    };
    auto storeS = [&]() {
#pragma unroll
        for (int j = 0; j < 4; j++) {
            int i = t + 256 * j;
            split_store(&As_hi[(i >> 3) * ASTRIDE + (i & 7) * 4],
                        &As_lo[(i >> 3) * ASTRIDE + (i & 7) * 4], ra[j]);
            split_store(&Bs_hi[(i >> 5) * BSTRIDE + (i & 31) * 4],
                        &Bs_lo[(i >> 5) * BSTRIDE + (i & 31) * 4], rb[j]);
        }
    };

    const int NSTAGE = C_DIM / BK;  // 24
    loadG(0);
    storeS();
    __syncthreads();
    for (int s = 0; s < NSTAGE; s++) {
        if (s + 1 < NSTAGE) loadG((s + 1) * BK);
        mma_stage(As_hi, As_lo, Bs_hi, Bs_lo, lane, wm, wn, acc);
        __syncthreads();
        if (s + 1 < NSTAGE) { storeS(); __syncthreads(); }
    }

    // epilogue: + b1, exact gelu, store fp32 h
    const int gid = lane >> 2, tg = lane & 3;
#pragma unroll
    for (int mi = 0; mi < 2; mi++) {
#pragma unroll
        for (int n8 = 0; n8 < 8; n8++) {
            int m = m0 + wm * 32 + mi * 16 + gid;
            int hc = h0 + wn * 64 + n8 * 8 + tg * 2;
            float bz0 = b1[e * H_DIM + hc];
            float bz1 = b1[e * H_DIM + hc + 1];
            float* a = acc[mi][n8];
            float2 v0 = {gelu_f(a[0] + bz0), gelu_f(a[1] + bz1)};
            float2 v1 = {gelu_f(a[2] + bz0), gelu_f(a[3] + bz1)};
            size_t base = ((size_t)e * N_TOK + m) * H_DIM + hc;
            *reinterpret_cast<float2*>(&g_h[base]) = v0;
            *reinterpret_cast<float2*>(&g_h[base + (size_t)8 * H_DIM]) = v1;
        }
    }
}

// ---------------- kernel 3: FFN2  part[g] = sum_{e in g} gate_e*(h_e @ w2_e) -
__global__ __launch_bounds__(256) void ffn2_kernel(const float* __restrict__ w2)
{
    __shared__ __nv_bfloat16 As_hi[BM * ASTRIDE], As_lo[BM * ASTRIDE];
    __shared__ __nv_bfloat16 Bs_hi[BK * BSTRIDE], Bs_lo[BK * BSTRIDE];

    const int m0 = blockIdx.x * BM;
    const int c0 = blockIdx.y * BN;
    const int grp = blockIdx.z;                  // 4 groups of 8 experts
    const int t = threadIdx.x, lane = t & 31, wid = t >> 5;
    const int wm = wid & 3, wn = wid >> 2;

    float acc[2][8][4];
#pragma unroll
    for (int mi = 0; mi < 2; mi++)
#pragma unroll
        for (int n8 = 0; n8 < 8; n8++)
#pragma unroll
            for (int q = 0; q < 4; q++) acc[mi][n8][q] = 0.0f;

    const int KST = H_DIM / BK;      // 96 stages per expert
    const int NSTAGE = 8 * KST;      // 768 total

    float4 ra[4], rb[4];
    auto loadG = [&](int s) {
        int e = grp * 8 + s / KST;
        int k0 = (s % KST) * BK;
        const float* w2e = w2 + (size_t)e * H_DIM * C_DIM;
#pragma unroll
        for (int j = 0; j < 4; j++) {
            int i = t + 256 * j;
            int row = i >> 3;
            float g = g_gates[(m0 + row) * E_NUM + e];
            float4 v = *reinterpret_cast<const float4*>(
                &g_h[((size_t)e * N_TOK + m0 + row) * H_DIM + k0 + (i & 7) * 4]);
            v.x *= g; v.y *= g; v.z *= g; v.w *= g;   // fold gate into A, then re-split
            ra[j] = v;
            rb[j] = *reinterpret_cast<const float4*>(
                w2e + (size_t)(k0 + (i >> 5)) * C_DIM + c0 + (i & 31) * 4);
        }
    };
    auto storeS = [&]() {
#pragma unroll
        for (int j = 0; j < 4; j++) {
            int i = t + 256 * j;
            split_store(&As_hi[(i >> 3) * ASTRIDE + (i & 7) * 4],
                        &As_lo[(i >> 3) * ASTRIDE + (i & 7) * 4], ra[j]);
            split_store(&Bs_hi[(i >> 5) * BSTRIDE + (i & 31) * 4],
                        &Bs_lo[(i >> 5) * BSTRIDE + (i & 31) * 4], rb[j]);
        }
    };

    loadG(0);
    storeS();
    __syncthreads();
    for (int s = 0; s < NSTAGE; s++) {
        if (s + 1 < NSTAGE) loadG(s + 1);
        mma_stage(As_hi, As_lo, Bs_hi, Bs_lo, lane, wm, wn, acc);
        __syncthreads();
        if (s + 1 < NSTAGE) { storeS(); __syncthreads(); }
    }

    const int gid = lane >> 2, tg = lane & 3;
#pragma unroll
    for (int mi = 0; mi < 2; mi++) {
#pragma unroll
        for (int n8 = 0; n8 < 8; n8++) {
            int m = m0 + wm * 32 + mi * 16 + gid;
            int cc = c0 + wn * 64 + n8 * 8 + tg * 2;
            float* a = acc[mi][n8];
            size_t base = ((size_t)grp * N_TOK + m) * C_DIM + cc;
            *reinterpret_cast<float2*>(&g_part[base]) = make_float2(a[0], a[1]);
            *reinterpret_cast<float2*>(&g_part[base + (size_t)8 * C_DIM]) = make_float2(a[2], a[3]);
        }
    }
}

// ---------------- kernel 4: finalize  out = sum_g part + sum_e gate*b2 ------
__global__ void finalize_kernel(const float* __restrict__ b2, float* __restrict__ out)
{
    int i = blockIdx.x * 256 + threadIdx.x;
    if (i >= N_TOK * C_DIM) return;
    int m = i / C_DIM, c = i % C_DIM;
    float s = g_part[i]
            + g_part[N_TOK * C_DIM + i]
            + g_part[2 * N_TOK * C_DIM + i]
            + g_part[3 * N_TOK * C_DIM + i];
    const float* gr = &g_gates[m * E_NUM];
#pragma unroll
    for (int e = 0; e < E_NUM; e++)
        s += gr[e] * b2[e * C_DIM + c];
    out[i] = s;
}

// ---------------- launch -----------------------------------------------------
extern "C" void kernel_launch(void* const* d_in, const int* in_sizes, int n_in,
                              void* d_out, int out_size)
{
    (void)in_sizes; (void)n_in; (void)out_size;
    const float* x      = (const float*)d_in[0];
    const float* gate_w = (const float*)d_in[1];
    const float* gate_b = (const float*)d_in[2];
    const float* w1     = (const float*)d_in[3];
    const float* b1     = (const float*)d_in[4];
    const float* w2     = (const float*)d_in[5];
    const float* b2     = (const float*)d_in[6];
    float* out = (float*)d_out;

    gate_kernel<<<N_TOK / 8, 256>>>(x, gate_w, gate_b);
    ffn1_kernel<<<dim3(N_TOK / BM, H_DIM / BN, E_NUM), 256>>>(x, w1, b1);
    ffn2_kernel<<<dim3(N_TOK / BM, C_DIM / BN, 4), 256>>>(w2);
    finalize_kernel<<<(N_TOK * C_DIM + 255) / 256, 256>>>(b2, out);
}

// round 7
// speedup vs baseline: 1.9648x; 1.3100x over previous
#include <cuda_runtime.h>
#include <cuda_bf16.h>
#include <cstdint>
#include <math.h>

#define N_TOK 2048
#define C_DIM 768
#define E_NUM 32
#define H_DIM 3072

#define BM 128
#define BN 128
#define BK 32
#define ASTRIDE 56     // 112B rows: 16B-aligned, ldmatrix conflict-free (28*r mod 32 distinct)
#define BSTRIDE 136    // 272B rows: 16B-aligned, ldmatrix.trans conflict-free (68*r mod 32 distinct)

#define A_ELTS (BM * ASTRIDE)              // 7168
#define B_ELTS (BK * BSTRIDE)              // 4352
#define STAGE_ELTS (2 * A_ELTS + 2 * B_ELTS)   // 23040 elts
#define NSTAGES 3
#define SMEM_BYTES (NSTAGES * STAGE_ELTS * 2)  // 138240 B

// ---------------- scratch (device globals; no allocation allowed) -----------
__device__ float g_gates[N_TOK * E_NUM];
__device__ __nv_bfloat16 g_x_hi[N_TOK * C_DIM];
__device__ __nv_bfloat16 g_x_lo[N_TOK * C_DIM];
__device__ __nv_bfloat16 g_w1_hi[(size_t)E_NUM * C_DIM * H_DIM];
__device__ __nv_bfloat16 g_w1_lo[(size_t)E_NUM * C_DIM * H_DIM];
__device__ __nv_bfloat16 g_w2_hi[(size_t)E_NUM * H_DIM * C_DIM];
__device__ __nv_bfloat16 g_w2_lo[(size_t)E_NUM * H_DIM * C_DIM];
__device__ __nv_bfloat16 g_h_hi[(size_t)E_NUM * N_TOK * H_DIM];
__device__ __nv_bfloat16 g_h_lo[(size_t)E_NUM * N_TOK * H_DIM];
__device__ float g_part[(size_t)E_NUM * N_TOK * C_DIM];

// ---------------- helpers ---------------------------------------------------
__device__ __forceinline__ uint32_t smem_u32(const void* p) {
    return (uint32_t)__cvta_generic_to_shared(p);
}
__device__ __forceinline__ void cp16(uint32_t s, const void* g) {
    asm volatile("cp.async.cg.shared.global [%0], [%1], 16;" :: "r"(s), "l"(g));
}
#define CP_COMMIT asm volatile("cp.async.commit_group;" ::: "memory")
#define CP_WAIT1  asm volatile("cp.async.wait_group 1;" ::: "memory")

__device__ __forceinline__ void ldm_x4(uint32_t r[4], uint32_t addr) {
    asm volatile("ldmatrix.sync.aligned.m8n8.x4.shared.b16 {%0,%1,%2,%3}, [%4];"
                 : "=r"(r[0]), "=r"(r[1]), "=r"(r[2]), "=r"(r[3]) : "r"(addr));
}
__device__ __forceinline__ void ldm_x4_t(uint32_t r[4], uint32_t addr) {
    asm volatile("ldmatrix.sync.aligned.m8n8.x4.trans.shared.b16 {%0,%1,%2,%3}, [%4];"
                 : "=r"(r[0]), "=r"(r[1]), "=r"(r[2]), "=r"(r[3]) : "r"(addr));
}
__device__ __forceinline__ void mma16816(float d[4], const uint32_t a[4], const uint32_t b[2]) {
    asm volatile("mma.sync.aligned.m16n8k16.row.col.f32.bf16.bf16.f32 "
                 "{%0,%1,%2,%3},{%4,%5,%6,%7},{%8,%9},{%0,%1,%2,%3};"
                 : "+f"(d[0]), "+f"(d[1]), "+f"(d[2]), "+f"(d[3])
                 : "r"(a[0]), "r"(a[1]), "r"(a[2]), "r"(a[3]), "r"(b[0]), "r"(b[1]));
}
__device__ __forceinline__ void split_pack(float4 v, uint2& hp, uint2& lp) {
    __nv_bfloat16 h0=__float2bfloat16(v.x), h1=__float2bfloat16(v.y);
    __nv_bfloat16 h2=__float2bfloat16(v.z), h3=__float2bfloat16(v.w);
    __nv_bfloat16 l0=__float2bfloat16(v.x-__bfloat162float(h0));
    __nv_bfloat16 l1=__float2bfloat16(v.y-__bfloat162float(h1));
    __nv_bfloat16 l2=__float2bfloat16(v.z-__bfloat162float(h2));
    __nv_bfloat16 l3=__float2bfloat16(v.w-__bfloat162float(h3));
    __nv_bfloat162 H01=__halves2bfloat162(h0,h1), H23=__halves2bfloat162(h2,h3);
    __nv_bfloat162 L01=__halves2bfloat162(l0,l1), L23=__halves2bfloat162(l2,l3);
    hp.x=*reinterpret_cast<uint32_t*>(&H01); hp.y=*reinterpret_cast<uint32_t*>(&H23);
    lp.x=*reinterpret_cast<uint32_t*>(&L01); lp.y=*reinterpret_cast<uint32_t*>(&L23);
}
__device__ __forceinline__ void split2(float x, float y, uint32_t& hp, uint32_t& lp) {
    __nv_bfloat16 hx=__float2bfloat16(x), hy=__float2bfloat16(y);
    __nv_bfloat16 lx=__float2bfloat16(x-__bfloat162float(hx));
    __nv_bfloat16 ly=__float2bfloat16(y-__bfloat162float(hy));
    __nv_bfloat162 H=__halves2bfloat162(hx,hy), L=__halves2bfloat162(lx,ly);
    hp=*reinterpret_cast<uint32_t*>(&H); lp=*reinterpret_cast<uint32_t*>(&L);
}
__device__ __forceinline__ float gelu_f(float v) {
    return 0.5f * v * (1.0f + erff(v * 0.70710678118654752f));
}

// 3-pass (hi*hi + hi*lo + lo*hi) MMA over one BK=32 stage.
// 8 warps 4(M)x2(N); per warp 32x64.
__device__ __forceinline__ void mma_stage(
    const __nv_bfloat16* As_hi, const __nv_bfloat16* As_lo,
    const __nv_bfloat16* Bs_hi, const __nv_bfloat16* Bs_lo,
    int lane, int wm, int wn, float acc[2][8][4])
{
#pragma unroll
    for (int kk = 0; kk < 2; kk++) {
        uint32_t ah[2][4], al[2][4];
#pragma unroll
        for (int mi = 0; mi < 2; mi++) {
            int off = (wm * 32 + mi * 16 + (lane & 15)) * ASTRIDE + kk * 16 + ((lane >> 4) << 3);
            ldm_x4(ah[mi], smem_u32(As_hi + off));
            ldm_x4(al[mi], smem_u32(As_lo + off));
        }
        uint32_t bh[4][4], bl[4][4];
#pragma unroll
        for (int nj = 0; nj < 4; nj++) {
            int off = (kk * 16 + (lane & 15)) * BSTRIDE + wn * 64 + nj * 16 + ((lane >> 4) << 3);
            ldm_x4_t(bh[nj], smem_u32(Bs_hi + off));
            ldm_x4_t(bl[nj], smem_u32(Bs_lo + off));
        }
#pragma unroll
        for (int mi = 0; mi < 2; mi++) {
#pragma unroll
            for (int n8 = 0; n8 < 8; n8++) {
                const uint32_t* Bh = &bh[n8 >> 1][(n8 & 1) * 2];
                const uint32_t* Bl = &bl[n8 >> 1][(n8 & 1) * 2];
                mma16816(acc[mi][n8], ah[mi], Bh);
                mma16816(acc[mi][n8], ah[mi], Bl);
                mma16816(acc[mi][n8], al[mi], Bh);
            }
        }
    }
}

// ---------------- kernel: fp32 -> hi/lo bf16 convert -------------------------
__global__ void convert_kernel(const float4* __restrict__ src,
                               uint2* __restrict__ hi, uint2* __restrict__ lo, int n4)
{
    int i = blockIdx.x * blockDim.x + threadIdx.x;
    if (i >= n4) return;
    uint2 hp, lp;
    split_pack(src[i], hp, lp);
    hi[i] = hp; lo[i] = lp;
}

// ---------------- kernel: gating softmax ------------------------------------
__global__ void gate_kernel(const float* __restrict__ x,
                            const float* __restrict__ gw,
                            const float* __restrict__ gb)
{
    int token = (blockIdx.x * blockDim.x + threadIdx.x) >> 5;
    int lane = threadIdx.x & 31;
    if (token >= N_TOK) return;
    const float* xr = x + (size_t)token * C_DIM;
    float acc = gb[lane];
#pragma unroll 4
    for (int k = 0; k < C_DIM; k++)
        acc = fmaf(xr[k], gw[k * E_NUM + lane], acc);
    float mx = acc;
#pragma unroll
    for (int o = 16; o > 0; o >>= 1) mx = fmaxf(mx, __shfl_xor_sync(0xffffffffu, mx, o));
    float ev = expf(acc - mx);
    float sm = ev;
#pragma unroll
    for (int o = 16; o > 0; o >>= 1) sm += __shfl_xor_sync(0xffffffffu, sm, o);
    g_gates[token * E_NUM + lane] = ev / sm;
}

// ---------------- main GEMM, cp.async 3-stage pipeline -----------------------
// MODE 0: h = gelu(x @ w1[e] + b1[e]) -> hi/lo bf16
// MODE 1: part[e] = gate * (h[e] @ w2[e])
template<int MODE>
__global__ __launch_bounds__(256, 1) void council_mma(const float* __restrict__ bias)
{
    extern __shared__ __nv_bfloat16 smem[];
    const int t = threadIdx.x, lane = t & 31, wid = t >> 5;
    const int wm = wid & 3, wn = wid >> 2;
    const int m0 = blockIdx.x * BM, n0 = blockIdx.y * BN, e = blockIdx.z;

    const size_t ldA = (MODE == 0) ? C_DIM : H_DIM;
    const size_t ldB = (MODE == 0) ? H_DIM : C_DIM;
    const int nstot = (int)(ldA / BK);   // 24 or 96

    const __nv_bfloat16* Ah = (MODE == 0) ? (g_x_hi + (size_t)m0 * C_DIM)
                                          : (g_h_hi + ((size_t)e * N_TOK + m0) * H_DIM);
    const __nv_bfloat16* Al = (MODE == 0) ? (g_x_lo + (size_t)m0 * C_DIM)
                                          : (g_h_lo + ((size_t)e * N_TOK + m0) * H_DIM);
    const __nv_bfloat16* Bh = (MODE == 0) ? (g_w1_hi + (size_t)e * C_DIM * H_DIM + n0)
                                          : (g_w2_hi + (size_t)e * H_DIM * C_DIM + n0);
    const __nv_bfloat16* Bl = (MODE == 0) ? (g_w1_lo + (size_t)e * C_DIM * H_DIM + n0)
                                          : (g_w2_lo + (size_t)e * H_DIM * C_DIM + n0);

    float acc[2][8][4];
#pragma unroll
    for (int mi = 0; mi < 2; mi++)
#pragma unroll
        for (int n8 = 0; n8 < 8; n8++)
#pragma unroll
            for (int q = 0; q < 4; q++) acc[mi][n8][q] = 0.0f;

    auto issue = [&](int s) {
        const int slot = s % NSTAGES;
        const uint32_t st = smem_u32(smem + (size_t)slot * STAGE_ELTS);
        const uint32_t sAh = st;
        const uint32_t sAl = sAh + A_ELTS * 2;
        const uint32_t sBh = sAl + A_ELTS * 2;
        const uint32_t sBl = sBh + B_ELTS * 2;
        const int k0 = s * BK;
#pragma unroll
        for (int j = 0; j < 2; j++) {
            int c = t + 256 * j;
            int r = c >> 2, kp = c & 3;                  // A: 128 rows x 4 chunks
            cp16(sAh + (r * ASTRIDE + kp * 8) * 2, Ah + (size_t)r * ldA + k0 + kp * 8);
            cp16(sAl + (r * ASTRIDE + kp * 8) * 2, Al + (size_t)r * ldA + k0 + kp * 8);
            int rk = c >> 4, np = c & 15;                // B: 32 rows x 16 chunks
            cp16(sBh + (rk * BSTRIDE + np * 8) * 2, Bh + (size_t)(k0 + rk) * ldB + np * 8);
            cp16(sBl + (rk * BSTRIDE + np * 8) * 2, Bl + (size_t)(k0 + rk) * ldB + np * 8);
        }
    };

    issue(0); CP_COMMIT;
    issue(1); CP_COMMIT;
    for (int s = 0; s < nstot; s++) {
        CP_WAIT1;
        __syncthreads();
        if (s + 2 < nstot) issue(s + 2);
        CP_COMMIT;
        const __nv_bfloat16* st = smem + (size_t)(s % NSTAGES) * STAGE_ELTS;
        mma_stage(st, st + A_ELTS, st + 2 * A_ELTS, st + 2 * A_ELTS + B_ELTS,
                  lane, wm, wn, acc);
    }

    // ---- epilogue ----
    const int gid = lane >> 2, tg = lane & 3;
#pragma unroll
    for (int mi = 0; mi < 2; mi++) {
        int m = m0 + wm * 32 + mi * 16 + gid;
        if (MODE == 0) {
#pragma unroll
            for (int n8 = 0; n8 < 8; n8++) {
                int n = n0 + wn * 64 + n8 * 8 + tg * 2;
                float b0 = bias[e * H_DIM + n], b1v = bias[e * H_DIM + n + 1];
                float* a = acc[mi][n8];
                uint32_t hp, lp;
                size_t gi = ((size_t)e * N_TOK + m) * H_DIM + n;
                split2(gelu_f(a[0] + b0), gelu_f(a[1] + b1v), hp, lp);
                *reinterpret_cast<uint32_t*>(&g_h_hi[gi]) = hp;
                *reinterpret_cast<uint32_t*>(&g_h_lo[gi]) = lp;
                split2(gelu_f(a[2] + b0), gelu_f(a[3] + b1v), hp, lp);
                *reinterpret_cast<uint32_t*>(&g_h_hi[gi + (size_t)8 * H_DIM]) = hp;
                *reinterpret_cast<uint32_t*>(&g_h_lo[gi + (size_t)8 * H_DIM]) = lp;
            }
        } else {
            float g0 = g_gates[m * E_NUM + e];
            float g1 = g_gates[(m + 8) * E_NUM + e];
#pragma unroll
            for (int n8 = 0; n8 < 8; n8++) {
                int n = n0 + wn * 64 + n8 * 8 + tg * 2;
                float* a = acc[mi][n8];
                size_t gi = (size_t)e * N_TOK * C_DIM + (size_t)m * C_DIM + n;
                *reinterpret_cast<float2*>(&g_part[gi]) = make_float2(a[0] * g0, a[1] * g0);
                *reinterpret_cast<float2*>(&g_part[gi + (size_t)8 * C_DIM]) =
                    make_float2(a[2] * g1, a[3] * g1);
            }
        }
    }
}

// ---------------- finalize ---------------------------------------------------
__global__ void finalize_kernel(const float* __restrict__ b2, float* __restrict__ out)
{
    int i4 = blockIdx.x * 256 + threadIdx.x;
    if (i4 >= N_TOK * C_DIM / 4) return;
    int i = i4 * 4, m = i / C_DIM, c = i % C_DIM;
    float4 s = make_float4(0.f, 0.f, 0.f, 0.f);
#pragma unroll 8
    for (int e = 0; e < E_NUM; e++) {
        float4 p = *(const float4*)&g_part[(size_t)e * N_TOK * C_DIM + i];
        float g = g_gates[m * E_NUM + e];
        const float* bb = &b2[e * C_DIM + c];
        s.x += p.x + g * bb[0]; s.y += p.y + g * bb[1];
        s.z += p.z + g * bb[2]; s.w += p.w + g * bb[3];
    }
    *(float4*)&out[i] = s;
}

// ---------------- launch -----------------------------------------------------
extern "C" void kernel_launch(void* const* d_in, const int* in_sizes, int n_in,
                              void* d_out, int out_size)
{
    (void)in_sizes; (void)n_in; (void)out_size;
    const float* x      = (const float*)d_in[0];
    const float* gate_w = (const float*)d_in[1];
    const float* gate_b = (const float*)d_in[2];
    const float* w1     = (const float*)d_in[3];
    const float* b1     = (const float*)d_in[4];
    const float* w2     = (const float*)d_in[5];
    const float* b2     = (const float*)d_in[6];
    float* out = (float*)d_out;

    static int attr_done = 0;
    if (!attr_done) {
        cudaFuncSetAttribute(council_mma<0>, cudaFuncAttributeMaxDynamicSharedMemorySize, SMEM_BYTES);
        cudaFuncSetAttribute(council_mma<1>, cudaFuncAttributeMaxDynamicSharedMemorySize, SMEM_BYTES);
        attr_done = 1;
    }

    __nv_bfloat16 *xh, *xl, *w1h, *w1l, *w2h, *w2l;
    cudaGetSymbolAddress((void**)&xh,  g_x_hi);  cudaGetSymbolAddress((void**)&xl,  g_x_lo);
    cudaGetSymbolAddress((void**)&w1h, g_w1_hi); cudaGetSymbolAddress((void**)&w1l, g_w1_lo);
    cudaGetSymbolAddress((void**)&w2h, g_w2_hi); cudaGetSymbolAddress((void**)&w2l, g_w2_lo);

    const int n4x  = N_TOK * C_DIM / 4;
    const int n4w  = (int)((size_t)E_NUM * C_DIM * H_DIM / 4);

    gate_kernel<<<N_TOK / 8, 256>>>(x, gate_w, gate_b);
    convert_kernel<<<(n4x + 255) / 256, 256>>>((const float4*)x, (uint2*)xh, (uint2*)xl, n4x);
    convert_kernel<<<(n4w + 255) / 256, 256>>>((const float4*)w1, (uint2*)w1h, (uint2*)w1l, n4w);
    convert_kernel<<<(n4w + 255) / 256, 256>>>((const float4*)w2, (uint2*)w2h, (uint2*)w2l, n4w);

    council_mma<0><<<dim3(N_TOK / BM, H_DIM / BN, E_NUM), 256, SMEM_BYTES>>>(b1);
    council_mma<1><<<dim3(N_TOK / BM, C_DIM / BN, E_NUM), 256, SMEM_BYTES>>>(nullptr);
    finalize_kernel<<<(N_TOK * C_DIM / 4 + 255) / 256, 256>>>(b2, out);
}

// round 8
// speedup vs baseline: 2.2728x; 1.1568x over previous
#include <cuda_runtime.h>
#include <cuda_bf16.h>
#include <cstdint>
#include <math.h>

#define N_TOK 2048
#define C_DIM 768
#define E_NUM 32
#define H_DIM 3072

#define BM 128
#define BN 256
#define BK 32
#define ASTRIDE 40     // 80B rows: 16B-aligned; ldmatrix conflict-free (20r mod 32 partitions banks)
#define BSTRIDE 264    // 528B rows: 16B-aligned; ldmatrix.trans conflict-free (4r steps, 16B-wide)

#define A_ELTS (BM * ASTRIDE)                  // 5120
#define B_ELTS (BK * BSTRIDE)                  // 8448
#define STAGE_ELTS (2 * A_ELTS + 2 * B_ELTS)   // 27136 elts
#define NSTAGES 3
#define SMEM_BYTES (NSTAGES * STAGE_ELTS * 2)  // 162816 B

// ---------------- scratch (device globals; no allocation allowed) -----------
__device__ float g_gates[N_TOK * E_NUM];
__device__ __nv_bfloat16 g_x_hi[N_TOK * C_DIM];
__device__ __nv_bfloat16 g_x_lo[N_TOK * C_DIM];
__device__ __nv_bfloat16 g_w1_hi[(size_t)E_NUM * C_DIM * H_DIM];
__device__ __nv_bfloat16 g_w1_lo[(size_t)E_NUM * C_DIM * H_DIM];
__device__ __nv_bfloat16 g_w2_hi[(size_t)E_NUM * H_DIM * C_DIM];
__device__ __nv_bfloat16 g_w2_lo[(size_t)E_NUM * H_DIM * C_DIM];
__device__ __nv_bfloat16 g_h_hi[(size_t)E_NUM * N_TOK * H_DIM];
__device__ __nv_bfloat16 g_h_lo[(size_t)E_NUM * N_TOK * H_DIM];
__device__ float g_part[(size_t)E_NUM * N_TOK * C_DIM];

// ---------------- helpers ---------------------------------------------------
__device__ __forceinline__ uint32_t smem_u32(const void* p) {
    return (uint32_t)__cvta_generic_to_shared(p);
}
__device__ __forceinline__ void cp16(uint32_t s, const void* g) {
    asm volatile("cp.async.cg.shared.global [%0], [%1], 16;" :: "r"(s), "l"(g));
}
#define CP_COMMIT asm volatile("cp.async.commit_group;" ::: "memory")
#define CP_WAIT1  asm volatile("cp.async.wait_group 1;" ::: "memory")

__device__ __forceinline__ void ldm_x4(uint32_t r[4], uint32_t addr) {
    asm volatile("ldmatrix.sync.aligned.m8n8.x4.shared.b16 {%0,%1,%2,%3}, [%4];"
                 : "=r"(r[0]), "=r"(r[1]), "=r"(r[2]), "=r"(r[3]) : "r"(addr));
}
__device__ __forceinline__ void ldm_x4_t(uint32_t r[4], uint32_t addr) {
    asm volatile("ldmatrix.sync.aligned.m8n8.x4.trans.shared.b16 {%0,%1,%2,%3}, [%4];"
                 : "=r"(r[0]), "=r"(r[1]), "=r"(r[2]), "=r"(r[3]) : "r"(addr));
}
__device__ __forceinline__ void mma16816(float d[4], const uint32_t a[4], const uint32_t b[2]) {
    asm volatile("mma.sync.aligned.m16n8k16.row.col.f32.bf16.bf16.f32 "
                 "{%0,%1,%2,%3},{%4,%5,%6,%7},{%8,%9},{%0,%1,%2,%3};"
                 : "+f"(d[0]), "+f"(d[1]), "+f"(d[2]), "+f"(d[3])
                 : "r"(a[0]), "r"(a[1]), "r"(a[2]), "r"(a[3]), "r"(b[0]), "r"(b[1]));
}
__device__ __forceinline__ void split_pack(float4 v, uint2& hp, uint2& lp) {
    __nv_bfloat16 h0=__float2bfloat16(v.x), h1=__float2bfloat16(v.y);
    __nv_bfloat16 h2=__float2bfloat16(v.z), h3=__float2bfloat16(v.w);
    __nv_bfloat16 l0=__float2bfloat16(v.x-__bfloat162float(h0));
    __nv_bfloat16 l1=__float2bfloat16(v.y-__bfloat162float(h1));
    __nv_bfloat16 l2=__float2bfloat16(v.z-__bfloat162float(h2));
    __nv_bfloat16 l3=__float2bfloat16(v.w-__bfloat162float(h3));
    __nv_bfloat162 H01=__halves2bfloat162(h0,h1), H23=__halves2bfloat162(h2,h3);
    __nv_bfloat162 L01=__halves2bfloat162(l0,l1), L23=__halves2bfloat162(l2,l3);
    hp.x=*reinterpret_cast<uint32_t*>(&H01); hp.y=*reinterpret_cast<uint32_t*>(&H23);
    lp.x=*reinterpret_cast<uint32_t*>(&L01); lp.y=*reinterpret_cast<uint32_t*>(&L23);
}
__device__ __forceinline__ void split2(float x, float y, uint32_t& hp, uint32_t& lp) {
    __nv_bfloat16 hx=__float2bfloat16(x), hy=__float2bfloat16(y);
    __nv_bfloat16 lx=__float2bfloat16(x-__bfloat162float(hx));
    __nv_bfloat16 ly=__float2bfloat16(y-__bfloat162float(hy));
    __nv_bfloat162 H=__halves2bfloat162(hx,hy), L=__halves2bfloat162(lx,ly);
    hp=*reinterpret_cast<uint32_t*>(&H); lp=*reinterpret_cast<uint32_t*>(&L);
}
__device__ __forceinline__ float gelu_f(float v) {
    return 0.5f * v * (1.0f + erff(v * 0.70710678118654752f));
}

// 3-pass (hi*hi + hi*lo + lo*hi) MMA over one BK=32 stage.
// 16 warps 4(M)x4(N); per warp 32x64.
__device__ __forceinline__ void mma_stage(
    const __nv_bfloat16* As_hi, const __nv_bfloat16* As_lo,
    const __nv_bfloat16* Bs_hi, const __nv_bfloat16* Bs_lo,
    int lane, int wm, int wn, float acc[2][8][4])
{
#pragma unroll
    for (int kk = 0; kk < 2; kk++) {
        uint32_t ah[2][4], al[2][4];
#pragma unroll
        for (int mi = 0; mi < 2; mi++) {
            int off = (wm * 32 + mi * 16 + (lane & 15)) * ASTRIDE + kk * 16 + ((lane >> 4) << 3);
            ldm_x4(ah[mi], smem_u32(As_hi + off));
            ldm_x4(al[mi], smem_u32(As_lo + off));
        }
        uint32_t bh[4][4], bl[4][4];
#pragma unroll
        for (int nj = 0; nj < 4; nj++) {
            int off = (kk * 16 + (lane & 15)) * BSTRIDE + wn * 64 + nj * 16 + ((lane >> 4) << 3);
            ldm_x4_t(bh[nj], smem_u32(Bs_hi + off));
            ldm_x4_t(bl[nj], smem_u32(Bs_lo + off));
        }
#pragma unroll
        for (int mi = 0; mi < 2; mi++) {
#pragma unroll
            for (int n8 = 0; n8 < 8; n8++) {
                const uint32_t* Bh = &bh[n8 >> 1][(n8 & 1) * 2];
                const uint32_t* Bl = &bl[n8 >> 1][(n8 & 1) * 2];
                mma16816(acc[mi][n8], ah[mi], Bh);
                mma16816(acc[mi][n8], ah[mi], Bl);
                mma16816(acc[mi][n8], al[mi], Bh);
            }
        }
    }
}

// ---------------- kernel: fp32 -> hi/lo bf16 convert -------------------------
__global__ void convert_kernel(const float4* __restrict__ src,
                               uint2* __restrict__ hi, uint2* __restrict__ lo, int n4)
{
    int i = blockIdx.x * blockDim.x + threadIdx.x;
    if (i >= n4) return;
    uint2 hp, lp;
    split_pack(src[i], hp, lp);
    hi[i] = hp; lo[i] = lp;
}

// ---------------- kernel: gating softmax ------------------------------------
__global__ void gate_kernel(const float* __restrict__ x,
                            const float* __restrict__ gw,
                            const float* __restrict__ gb)
{
    int token = (blockIdx.x * blockDim.x + threadIdx.x) >> 5;
    int lane = threadIdx.x & 31;
    if (token >= N_TOK) return;
    const float* xr = x + (size_t)token * C_DIM;
    float acc = gb[lane];
#pragma unroll 4
    for (int k = 0; k < C_DIM; k++)
        acc = fmaf(xr[k], gw[k * E_NUM + lane], acc);
    float mx = acc;
#pragma unroll
    for (int o = 16; o > 0; o >>= 1) mx = fmaxf(mx, __shfl_xor_sync(0xffffffffu, mx, o));
    float ev = expf(acc - mx);
    float sm = ev;
#pragma unroll
    for (int o = 16; o > 0; o >>= 1) sm += __shfl_xor_sync(0xffffffffu, sm, o);
    g_gates[token * E_NUM + lane] = ev / sm;
}

// ---------------- main GEMM, cp.async 3-stage pipeline -----------------------
// MODE 0: h = gelu(x @ w1[e] + b1[e]) -> hi/lo bf16
// MODE 1: part[e] = gate * (h[e] @ w2[e])
template<int MODE>
__global__ __launch_bounds__(512, 1) void council_mma(const float* __restrict__ bias)
{
    extern __shared__ __nv_bfloat16 smem[];
    const int t = threadIdx.x, lane = t & 31, wid = t >> 5;
    const int wm = wid & 3, wn = wid >> 2;
    const int m0 = blockIdx.x * BM, n0 = blockIdx.y * BN, e = blockIdx.z;

    const size_t ldA = (MODE == 0) ? C_DIM : H_DIM;
    const size_t ldB = (MODE == 0) ? H_DIM : C_DIM;
    const int nstot = (int)(ldA / BK);   // 24 or 96

    const __nv_bfloat16* Ah = (MODE == 0) ? (g_x_hi + (size_t)m0 * C_DIM)
                                          : (g_h_hi + ((size_t)e * N_TOK + m0) * H_DIM);
    const __nv_bfloat16* Al = (MODE == 0) ? (g_x_lo + (size_t)m0 * C_DIM)
                                          : (g_h_lo + ((size_t)e * N_TOK + m0) * H_DIM);
    const __nv_bfloat16* Bh = (MODE == 0) ? (g_w1_hi + (size_t)e * C_DIM * H_DIM + n0)
                                          : (g_w2_hi + (size_t)e * H_DIM * C_DIM + n0);
    const __nv_bfloat16* Bl = (MODE == 0) ? (g_w1_lo + (size_t)e * C_DIM * H_DIM + n0)
                                          : (g_w2_lo + (size_t)e * H_DIM * C_DIM + n0);

    float acc[2][8][4];
#pragma unroll
    for (int mi = 0; mi < 2; mi++)
#pragma unroll
        for (int n8 = 0; n8 < 8; n8++)
#pragma unroll
            for (int q = 0; q < 4; q++) acc[mi][n8][q] = 0.0f;

    auto issue = [&](int s) {
        const int slot = s % NSTAGES;
        const uint32_t st = smem_u32(smem + (size_t)slot * STAGE_ELTS);
        const uint32_t sAh = st;
        const uint32_t sAl = sAh + A_ELTS * 2;
        const uint32_t sBh = sAl + A_ELTS * 2;
        const uint32_t sBl = sBh + B_ELTS * 2;
        const int k0 = s * BK;
        {   // A: 128 rows x 4 chunks of 8 elts, 512 threads -> 1 each
            int r = t >> 2, kp = t & 3;
            cp16(sAh + (r * ASTRIDE + kp * 8) * 2, Ah + (size_t)r * ldA + k0 + kp * 8);
            cp16(sAl + (r * ASTRIDE + kp * 8) * 2, Al + (size_t)r * ldA + k0 + kp * 8);
        }
#pragma unroll
        for (int j = 0; j < 2; j++) {   // B: 32 rows x 32 chunks -> 2 each
            int c = t + 512 * j;
            int rk = c >> 5, np = c & 31;
            cp16(sBh + (rk * BSTRIDE + np * 8) * 2, Bh + (size_t)(k0 + rk) * ldB + np * 8);
            cp16(sBl + (rk * BSTRIDE + np * 8) * 2, Bl + (size_t)(k0 + rk) * ldB + np * 8);
        }
    };

    issue(0); CP_COMMIT;
    issue(1); CP_COMMIT;
    for (int s = 0; s < nstot; s++) {
        CP_WAIT1;
        __syncthreads();
        if (s + 2 < nstot) issue(s + 2);
        CP_COMMIT;
        const __nv_bfloat16* st = smem + (size_t)(s % NSTAGES) * STAGE_ELTS;
        mma_stage(st, st + A_ELTS, st + 2 * A_ELTS, st + 2 * A_ELTS + B_ELTS,
                  lane, wm, wn, acc);
    }

    // ---- epilogue ----
    const int gid = lane >> 2, tg = lane & 3;
#pragma unroll
    for (int mi = 0; mi < 2; mi++) {
        int m = m0 + wm * 32 + mi * 16 + gid;
        if (MODE == 0) {
#pragma unroll
            for (int n8 = 0; n8 < 8; n8++) {
                int n = n0 + wn * 64 + n8 * 8 + tg * 2;
                float b0 = bias[e * H_DIM + n], b1v = bias[e * H_DIM + n + 1];
                float* a = acc[mi][n8];
                uint32_t hp, lp;
                size_t gi = ((size_t)e * N_TOK + m) * H_DIM + n;
                split2(gelu_f(a[0] + b0), gelu_f(a[1] + b1v), hp, lp);
                *reinterpret_cast<uint32_t*>(&g_h_hi[gi]) = hp;
                *reinterpret_cast<uint32_t*>(&g_h_lo[gi]) = lp;
                split2(gelu_f(a[2] + b0), gelu_f(a[3] + b1v), hp, lp);
                *reinterpret_cast<uint32_t*>(&g_h_hi[gi + (size_t)8 * H_DIM]) = hp;
                *reinterpret_cast<uint32_t*>(&g_h_lo[gi + (size_t)8 * H_DIM]) = lp;
            }
        } else {
            float g0 = g_gates[m * E_NUM + e];
            float g1 = g_gates[(m + 8) * E_NUM + e];
#pragma unroll
            for (int n8 = 0; n8 < 8; n8++) {
                int n = n0 + wn * 64 + n8 * 8 + tg * 2;
                float* a = acc[mi][n8];
                size_t gi = (size_t)e * N_TOK * C_DIM + (size_t)m * C_DIM + n;
                *reinterpret_cast<float2*>(&g_part[gi]) = make_float2(a[0] * g0, a[1] * g0);
                *reinterpret_cast<float2*>(&g_part[gi + (size_t)8 * C_DIM]) =
                    make_float2(a[2] * g1, a[3] * g1);
            }
        }
    }
}

// ---------------- finalize ---------------------------------------------------
__global__ void finalize_kernel(const float* __restrict__ b2, float* __restrict__ out)
{
    int i4 = blockIdx.x * 256 + threadIdx.x;
    if (i4 >= N_TOK * C_DIM / 4) return;
    int i = i4 * 4, m = i / C_DIM, c = i % C_DIM;
    float4 s = make_float4(0.f, 0.f, 0.f, 0.f);
#pragma unroll 8
    for (int e = 0; e < E_NUM; e++) {
        float4 p = *(const float4*)&g_part[(size_t)e * N_TOK * C_DIM + i];
        float g = g_gates[m * E_NUM + e];
        const float* bb = &b2[e * C_DIM + c];
        s.x += p.x + g * bb[0]; s.y += p.y + g * bb[1];
        s.z += p.z + g * bb[2]; s.w += p.w + g * bb[3];
    }
    *(float4*)&out[i] = s;
}

// ---------------- launch -----------------------------------------------------
extern "C" void kernel_launch(void* const* d_in, const int* in_sizes, int n_in,
                              void* d_out, int out_size)
{
    (void)in_sizes; (void)n_in; (void)out_size;
    const float* x      = (const float*)d_in[0];
    const float* gate_w = (const float*)d_in[1];
    const float* gate_b = (const float*)d_in[2];
    const float* w1     = (const float*)d_in[3];
    const float* b1     = (const float*)d_in[4];
    const float* w2     = (const float*)d_in[5];
    const float* b2     = (const float*)d_in[6];
    float* out = (float*)d_out;

    static int attr_done = 0;
    if (!attr_done) {
        cudaFuncSetAttribute(council_mma<0>, cudaFuncAttributeMaxDynamicSharedMemorySize, SMEM_BYTES);
        cudaFuncSetAttribute(council_mma<1>, cudaFuncAttributeMaxDynamicSharedMemorySize, SMEM_BYTES);
        attr_done = 1;
    }

    __nv_bfloat16 *xh, *xl, *w1h, *w1l, *w2h, *w2l;
    cudaGetSymbolAddress((void**)&xh,  g_x_hi);  cudaGetSymbolAddress((void**)&xl,  g_x_lo);
    cudaGetSymbolAddress((void**)&w1h, g_w1_hi); cudaGetSymbolAddress((void**)&w1l, g_w1_lo);
    cudaGetSymbolAddress((void**)&w2h, g_w2_hi); cudaGetSymbolAddress((void**)&w2l, g_w2_lo);

    const int n4x  = N_TOK * C_DIM / 4;
    const int n4w  = (int)((size_t)E_NUM * C_DIM * H_DIM / 4);

    gate_kernel<<<N_TOK / 8, 256>>>(x, gate_w, gate_b);
    convert_kernel<<<(n4x + 255) / 256, 256>>>((const float4*)x, (uint2*)xh, (uint2*)xl, n4x);
    convert_kernel<<<(n4w + 255) / 256, 256>>>((const float4*)w1, (uint2*)w1h, (uint2*)w1l, n4w);
    convert_kernel<<<(n4w + 255) / 256, 256>>>((const float4*)w2, (uint2*)w2h, (uint2*)w2l, n4w);

    council_mma<0><<<dim3(N_TOK / BM, H_DIM / BN, E_NUM), 512, SMEM_BYTES>>>(b1);
    council_mma<1><<<dim3(N_TOK / BM, C_DIM / BN, E_NUM), 512, SMEM_BYTES>>>(nullptr);
    finalize_kernel<<<(N_TOK * C_DIM / 4 + 255) / 256, 256>>>(b2, out);
}

// round 9
// speedup vs baseline: 4.7609x; 2.0947x over previous
#include <cuda_runtime.h>
#include <cuda_fp16.h>
#include <cstdint>
#include <math.h>

#define N_TOK 2048
#define C_DIM 768
#define E_NUM 32
#define H_DIM 3072

#define BM 128
#define BN 256
#define BK 32
#define ASTRIDE 40     // 80B rows: 16B-aligned; ldmatrix conflict-free
#define BSTRIDE 264    // 528B rows: 16B-aligned; ldmatrix.trans conflict-free

#define A_ELTS (BM * ASTRIDE)              // 5120
#define B_ELTS (BK * BSTRIDE)              // 8448
#define STAGE_ELTS (A_ELTS + B_ELTS)       // 13568 elts (fp16)
#define NSTAGES 5
#define SMEM_BYTES (NSTAGES * STAGE_ELTS * 2)  // 135680 B

// ---------------- scratch (device globals; no allocation allowed) -----------
__device__ float g_gates[N_TOK * E_NUM];
__device__ __half g_x16[N_TOK * C_DIM];
__device__ __half g_w1h[(size_t)E_NUM * C_DIM * H_DIM];
__device__ __half g_w2h[(size_t)E_NUM * H_DIM * C_DIM];
__device__ __half g_h16[(size_t)E_NUM * N_TOK * H_DIM];
__device__ float g_part[(size_t)E_NUM * N_TOK * C_DIM];

// ---------------- helpers ---------------------------------------------------
__device__ __forceinline__ uint32_t smem_u32(const void* p) {
    return (uint32_t)__cvta_generic_to_shared(p);
}
__device__ __forceinline__ void cp16(uint32_t s, const void* g) {
    asm volatile("cp.async.cg.shared.global [%0], [%1], 16;" :: "r"(s), "l"(g));
}
#define CP_COMMIT asm volatile("cp.async.commit_group;" ::: "memory")
#define CP_WAIT3  asm volatile("cp.async.wait_group 3;" ::: "memory")

__device__ __forceinline__ void ldm_x4(uint32_t r[4], uint32_t addr) {
    asm volatile("ldmatrix.sync.aligned.m8n8.x4.shared.b16 {%0,%1,%2,%3}, [%4];"
                 : "=r"(r[0]), "=r"(r[1]), "=r"(r[2]), "=r"(r[3]) : "r"(addr));
}
__device__ __forceinline__ void ldm_x4_t(uint32_t r[4], uint32_t addr) {
    asm volatile("ldmatrix.sync.aligned.m8n8.x4.trans.shared.b16 {%0,%1,%2,%3}, [%4];"
                 : "=r"(r[0]), "=r"(r[1]), "=r"(r[2]), "=r"(r[3]) : "r"(addr));
}
__device__ __forceinline__ void mma16816(float d[4], const uint32_t a[4], const uint32_t b[2]) {
    asm volatile("mma.sync.aligned.m16n8k16.row.col.f32.f16.f16.f32 "
                 "{%0,%1,%2,%3},{%4,%5,%6,%7},{%8,%9},{%0,%1,%2,%3};"
                 : "+f"(d[0]), "+f"(d[1]), "+f"(d[2]), "+f"(d[3])
                 : "r"(a[0]), "r"(a[1]), "r"(a[2]), "r"(a[3]), "r"(b[0]), "r"(b[1]));
}
__device__ __forceinline__ uint2 pack_h4(float4 v) {
    __half2 a = __floats2half2_rn(v.x, v.y);
    __half2 b = __floats2half2_rn(v.z, v.w);
    uint2 r;
    r.x = *reinterpret_cast<uint32_t*>(&a);
    r.y = *reinterpret_cast<uint32_t*>(&b);
    return r;
}
__device__ __forceinline__ float gelu_f(float v) {
    return 0.5f * v * (1.0f + erff(v * 0.70710678118654752f));
}

// single-pass fp16 MMA over one BK=32 stage.
// 16 warps 4(M)x4(N); per warp 32x64.
__device__ __forceinline__ void mma_stage(
    const __half* As, const __half* Bs,
    int lane, int wm, int wn, float acc[2][8][4])
{
#pragma unroll
    for (int kk = 0; kk < 2; kk++) {
        uint32_t a[2][4];
#pragma unroll
        for (int mi = 0; mi < 2; mi++) {
            int off = (wm * 32 + mi * 16 + (lane & 15)) * ASTRIDE + kk * 16 + ((lane >> 4) << 3);
            ldm_x4(a[mi], smem_u32(As + off));
        }
        uint32_t b[4][4];
#pragma unroll
        for (int nj = 0; nj < 4; nj++) {
            int off = (kk * 16 + (lane & 15)) * BSTRIDE + wn * 64 + nj * 16 + ((lane >> 4) << 3);
            ldm_x4_t(b[nj], smem_u32(Bs + off));
        }
#pragma unroll
        for (int mi = 0; mi < 2; mi++) {
#pragma unroll
            for (int n8 = 0; n8 < 8; n8++) {
                mma16816(acc[mi][n8], a[mi], &b[n8 >> 1][(n8 & 1) * 2]);
            }
        }
    }
}

// ---------------- kernel: fp32 -> fp16 convert -------------------------------
__global__ void convert_kernel(const float4* __restrict__ src,
                               uint2* __restrict__ dst, int n4)
{
    int i = blockIdx.x * blockDim.x + threadIdx.x;
    if (i >= n4) return;
    dst[i] = pack_h4(src[i]);
}

// ---------------- kernel: gating softmax ------------------------------------
__global__ void gate_kernel(const float* __restrict__ x,
                            const float* __restrict__ gw,
                            const float* __restrict__ gb)
{
    int token = (blockIdx.x * blockDim.x + threadIdx.x) >> 5;
    int lane = threadIdx.x & 31;
    if (token >= N_TOK) return;
    const float* xr = x + (size_t)token * C_DIM;
    float acc = gb[lane];
#pragma unroll 4
    for (int k = 0; k < C_DIM; k++)
        acc = fmaf(xr[k], gw[k * E_NUM + lane], acc);
    float mx = acc;
#pragma unroll
    for (int o = 16; o > 0; o >>= 1) mx = fmaxf(mx, __shfl_xor_sync(0xffffffffu, mx, o));
    float ev = expf(acc - mx);
    float sm = ev;
#pragma unroll
    for (int o = 16; o > 0; o >>= 1) sm += __shfl_xor_sync(0xffffffffu, sm, o);
    g_gates[token * E_NUM + lane] = ev / sm;
}

// ---------------- main GEMM, cp.async 5-stage pipeline -----------------------
// MODE 0: h = gelu(x @ w1[e] + b1[e]) -> fp16
// MODE 1: part[e] = gate * (h[e] @ w2[e])
template<int MODE>
__global__ __launch_bounds__(512, 1) void council_mma(const float* __restrict__ bias)
{
    extern __shared__ __half smem[];
    const int t = threadIdx.x, lane = t & 31, wid = t >> 5;
    const int wm = wid & 3, wn = wid >> 2;
    const int m0 = blockIdx.x * BM, n0 = blockIdx.y * BN, e = blockIdx.z;

    const size_t ldA = (MODE == 0) ? C_DIM : H_DIM;
    const size_t ldB = (MODE == 0) ? H_DIM : C_DIM;
    const int nstot = (int)(ldA / BK);   // 24 or 96

    const __half* Ag = (MODE == 0) ? (g_x16 + (size_t)m0 * C_DIM)
                                   : (g_h16 + ((size_t)e * N_TOK + m0) * H_DIM);
    const __half* Bg = (MODE == 0) ? (g_w1h + (size_t)e * C_DIM * H_DIM + n0)
                                   : (g_w2h + (size_t)e * H_DIM * C_DIM + n0);

    float acc[2][8][4];
#pragma unroll
    for (int mi = 0; mi < 2; mi++)
#pragma unroll
        for (int n8 = 0; n8 < 8; n8++)
#pragma unroll
            for (int q = 0; q < 4; q++) acc[mi][n8][q] = 0.0f;

    auto issue = [&](int s) {
        const int slot = s % NSTAGES;
        const uint32_t sA = smem_u32(smem + (size_t)slot * STAGE_ELTS);
        const uint32_t sB = sA + A_ELTS * 2;
        const int k0 = s * BK;
        {   // A: 128 rows x 4 chunks of 8 elts = 512 cp16 -> 1 per thread
            int r = t >> 2, kp = t & 3;
            cp16(sA + (r * ASTRIDE + kp * 8) * 2, Ag + (size_t)r * ldA + k0 + kp * 8);
        }
#pragma unroll
        for (int j = 0; j < 2; j++) {   // B: 32 rows x 32 chunks = 1024 cp16 -> 2 per thread
            int c = t + 512 * j;
            int rk = c >> 5, np = c & 31;
            cp16(sB + (rk * BSTRIDE + np * 8) * 2, Bg + (size_t)(k0 + rk) * ldB + np * 8);
        }
    };

    issue(0); CP_COMMIT;
    issue(1); CP_COMMIT;
    issue(2); CP_COMMIT;
    issue(3); CP_COMMIT;
    for (int s = 0; s < nstot; s++) {
        CP_WAIT3;
        __syncthreads();
        if (s + 4 < nstot) issue(s + 4);
        CP_COMMIT;
        const __half* st = smem + (size_t)(s % NSTAGES) * STAGE_ELTS;
        mma_stage(st, st + A_ELTS, lane, wm, wn, acc);
    }

    // ---- epilogue ----
    const int gid = lane >> 2, tg = lane & 3;
#pragma unroll
    for (int mi = 0; mi < 2; mi++) {
        int m = m0 + wm * 32 + mi * 16 + gid;
        if (MODE == 0) {
#pragma unroll
            for (int n8 = 0; n8 < 8; n8++) {
                int n = n0 + wn * 64 + n8 * 8 + tg * 2;
                float b0 = bias[e * H_DIM + n], b1v = bias[e * H_DIM + n + 1];
                float* a = acc[mi][n8];
                size_t gi = ((size_t)e * N_TOK + m) * H_DIM + n;
                __half2 v0 = __floats2half2_rn(gelu_f(a[0] + b0), gelu_f(a[1] + b1v));
                __half2 v1 = __floats2half2_rn(gelu_f(a[2] + b0), gelu_f(a[3] + b1v));
                *reinterpret_cast<__half2*>(&g_h16[gi]) = v0;
                *reinterpret_cast<__half2*>(&g_h16[gi + (size_t)8 * H_DIM]) = v1;
            }
        } else {
            float g0 = g_gates[m * E_NUM + e];
            float g1 = g_gates[(m + 8) * E_NUM + e];
#pragma unroll
            for (int n8 = 0; n8 < 8; n8++) {
                int n = n0 + wn * 64 + n8 * 8 + tg * 2;
                float* a = acc[mi][n8];
                size_t gi = (size_t)e * N_TOK * C_DIM + (size_t)m * C_DIM + n;
                *reinterpret_cast<float2*>(&g_part[gi]) = make_float2(a[0] * g0, a[1] * g0);
                *reinterpret_cast<float2*>(&g_part[gi + (size_t)8 * C_DIM]) =
                    make_float2(a[2] * g1, a[3] * g1);
            }
        }
    }
}

// ---------------- finalize ---------------------------------------------------
__global__ void finalize_kernel(const float* __restrict__ b2, float* __restrict__ out)
{
    int i4 = blockIdx.x * 256 + threadIdx.x;
    if (i4 >= N_TOK * C_DIM / 4) return;
    int i = i4 * 4, m = i / C_DIM, c = i % C_DIM;
    float4 s = make_float4(0.f, 0.f, 0.f, 0.f);
#pragma unroll 8
    for (int e = 0; e < E_NUM; e++) {
        float4 p = *(const float4*)&g_part[(size_t)e * N_TOK * C_DIM + i];
        float g = g_gates[m * E_NUM + e];
        const float* bb = &b2[e * C_DIM + c];
        s.x += p.x + g * bb[0]; s.y += p.y + g * bb[1];
        s.z += p.z + g * bb[2]; s.w += p.w + g * bb[3];
    }
    *(float4*)&out[i] = s;
}

// ---------------- launch -----------------------------------------------------
extern "C" void kernel_launch(void* const* d_in, const int* in_sizes, int n_in,
                              void* d_out, int out_size)
{
    (void)in_sizes; (void)n_in; (void)out_size;
    const float* x      = (const float*)d_in[0];
    const float* gate_w = (const float*)d_in[1];
    const float* gate_b = (const float*)d_in[2];
    const float* w1     = (const float*)d_in[3];
    const float* b1     = (const float*)d_in[4];
    const float* w2     = (const float*)d_in[5];
    const float* b2     = (const float*)d_in[6];
    float* out = (float*)d_out;

    static int attr_done = 0;
    if (!attr_done) {
        cudaFuncSetAttribute(council_mma<0>, cudaFuncAttributeMaxDynamicSharedMemorySize, SMEM_BYTES);
        cudaFuncSetAttribute(council_mma<1>, cudaFuncAttributeMaxDynamicSharedMemorySize, SMEM_BYTES);
        attr_done = 1;
    }

    __half *xh, *w1h, *w2h;
    cudaGetSymbolAddress((void**)&xh,  g_x16);
    cudaGetSymbolAddress((void**)&w1h, g_w1h);
    cudaGetSymbolAddress((void**)&w2h, g_w2h);

    const int n4x = N_TOK * C_DIM / 4;
    const int n4w = (int)((size_t)E_NUM * C_DIM * H_DIM / 4);

    gate_kernel<<<N_TOK / 8, 256>>>(x, gate_w, gate_b);
    convert_kernel<<<(n4x + 255) / 256, 256>>>((const float4*)x, (uint2*)xh, n4x);
    convert_kernel<<<(n4w + 255) / 256, 256>>>((const float4*)w1, (uint2*)w1h, n4w);
    convert_kernel<<<(n4w + 255) / 256, 256>>>((const float4*)w2, (uint2*)w2h, n4w);

    council_mma<0><<<dim3(N_TOK / BM, H_DIM / BN, E_NUM), 512, SMEM_BYTES>>>(b1);
    council_mma<1><<<dim3(N_TOK / BM, C_DIM / BN, E_NUM), 512, SMEM_BYTES>>>(nullptr);
    finalize_kernel<<<(N_TOK * C_DIM / 4 + 255) / 256, 256>>>(b2, out);
}

// round 10
// speedup vs baseline: 5.4122x; 1.1368x over previous
#include <cuda_runtime.h>
#include <cuda_fp16.h>
#include <cstdint>
#include <math.h>

#define N_TOK 2048
#define C_DIM 768
#define E_NUM 32
#define H_DIM 3072

#define BM 128
#define BN 128
#define BK 32
#define ASTRIDE 40     // 80B rows: 16B-aligned; ldmatrix conflict-free
#define BSTRIDE 136    // 272B rows: 16B-aligned; ldmatrix.trans conflict-free

#define A_ELTS (BM * ASTRIDE)              // 5120
#define B_ELTS (BK * BSTRIDE)              // 4352
#define STAGE_ELTS (A_ELTS + B_ELTS)       // 9472 elts (fp16)
#define NSTAGES 5
#define SMEM_BYTES (NSTAGES * STAGE_ELTS * 2)  // 94720 B -> 2 CTAs/SM

// ---------------- scratch (device globals; no allocation allowed) -----------
__device__ float g_gates[N_TOK * E_NUM];
__device__ __half g_x16[N_TOK * C_DIM];
__device__ __half g_w1h[(size_t)E_NUM * C_DIM * H_DIM];
__device__ __half g_w2h[(size_t)E_NUM * H_DIM * C_DIM];
__device__ __half g_h16[(size_t)E_NUM * N_TOK * H_DIM];
__device__ float g_part[(size_t)E_NUM * N_TOK * C_DIM];

// ---------------- helpers ---------------------------------------------------
__device__ __forceinline__ uint32_t smem_u32(const void* p) {
    return (uint32_t)__cvta_generic_to_shared(p);
}
__device__ __forceinline__ void cp16(uint32_t s, const void* g) {
    asm volatile("cp.async.cg.shared.global [%0], [%1], 16;" :: "r"(s), "l"(g));
}
#define CP_COMMIT asm volatile("cp.async.commit_group;" ::: "memory")
#define CP_WAIT3  asm volatile("cp.async.wait_group 3;" ::: "memory")

__device__ __forceinline__ void ldm_x4(uint32_t r[4], uint32_t addr) {
    asm volatile("ldmatrix.sync.aligned.m8n8.x4.shared.b16 {%0,%1,%2,%3}, [%4];"
                 : "=r"(r[0]), "=r"(r[1]), "=r"(r[2]), "=r"(r[3]) : "r"(addr));
}
__device__ __forceinline__ void ldm_x4_t(uint32_t r[4], uint32_t addr) {
    asm volatile("ldmatrix.sync.aligned.m8n8.x4.trans.shared.b16 {%0,%1,%2,%3}, [%4];"
                 : "=r"(r[0]), "=r"(r[1]), "=r"(r[2]), "=r"(r[3]) : "r"(addr));
}
__device__ __forceinline__ void mma16816(float d[4], const uint32_t a[4], const uint32_t b[2]) {
    asm volatile("mma.sync.aligned.m16n8k16.row.col.f32.f16.f16.f32 "
                 "{%0,%1,%2,%3},{%4,%5,%6,%7},{%8,%9},{%0,%1,%2,%3};"
                 : "+f"(d[0]), "+f"(d[1]), "+f"(d[2]), "+f"(d[3])
                 : "r"(a[0]), "r"(a[1]), "r"(a[2]), "r"(a[3]), "r"(b[0]), "r"(b[1]));
}
__device__ __forceinline__ uint2 pack_h4(float4 v) {
    __half2 a = __floats2half2_rn(v.x, v.y);
    __half2 b = __floats2half2_rn(v.z, v.w);
    uint2 r;
    r.x = *reinterpret_cast<uint32_t*>(&a);
    r.y = *reinterpret_cast<uint32_t*>(&b);
    return r;
}
__device__ __forceinline__ float gelu_f(float v) {
    return 0.5f * v * (1.0f + erff(v * 0.70710678118654752f));
}

// single-pass fp16 MMA over one BK=32 stage.
// 8 warps 4(M)x2(N); per warp 32x64.
__device__ __forceinline__ void mma_stage(
    const __half* As, const __half* Bs,
    int lane, int wm, int wn, float acc[2][8][4])
{
#pragma unroll
    for (int kk = 0; kk < 2; kk++) {
        uint32_t a[2][4];
#pragma unroll
        for (int mi = 0; mi < 2; mi++) {
            int off = (wm * 32 + mi * 16 + (lane & 15)) * ASTRIDE + kk * 16 + ((lane >> 4) << 3);
            ldm_x4(a[mi], smem_u32(As + off));
        }
        uint32_t b[4][4];
#pragma unroll
        for (int nj = 0; nj < 4; nj++) {
            int off = (kk * 16 + (lane & 15)) * BSTRIDE + wn * 64 + nj * 16 + ((lane >> 4) << 3);
            ldm_x4_t(b[nj], smem_u32(Bs + off));
        }
#pragma unroll
        for (int mi = 0; mi < 2; mi++) {
#pragma unroll
            for (int n8 = 0; n8 < 8; n8++) {
                mma16816(acc[mi][n8], a[mi], &b[n8 >> 1][(n8 & 1) * 2]);
            }
        }
    }
}

// ---------------- kernel: fp32 -> fp16 convert -------------------------------
__global__ void convert_kernel(const float4* __restrict__ src,
                               uint2* __restrict__ dst, int n4)
{
    int i = blockIdx.x * blockDim.x + threadIdx.x;
    if (i >= n4) return;
    dst[i] = pack_h4(src[i]);
}

// ---------------- kernel: gating softmax ------------------------------------
__global__ void gate_kernel(const float* __restrict__ x,
                            const float* __restrict__ gw,
                            const float* __restrict__ gb)
{
    int token = (blockIdx.x * blockDim.x + threadIdx.x) >> 5;
    int lane = threadIdx.x & 31;
    if (token >= N_TOK) return;
    const float* xr = x + (size_t)token * C_DIM;
    float acc = gb[lane];
#pragma unroll 4
    for (int k = 0; k < C_DIM; k++)
        acc = fmaf(xr[k], gw[k * E_NUM + lane], acc);
    float mx = acc;
#pragma unroll
    for (int o = 16; o > 0; o >>= 1) mx = fmaxf(mx, __shfl_xor_sync(0xffffffffu, mx, o));
    float ev = expf(acc - mx);
    float sm = ev;
#pragma unroll
    for (int o = 16; o > 0; o >>= 1) sm += __shfl_xor_sync(0xffffffffu, sm, o);
    g_gates[token * E_NUM + lane] = ev / sm;
}

// ---------------- main GEMM, cp.async 5-stage pipeline, 2 CTAs/SM -----------
// MODE 0: h = gelu(x @ w1[e] + b1[e]) -> fp16
// MODE 1: part[e] = gate * (h[e] @ w2[e])
template<int MODE>
__global__ __launch_bounds__(256, 2) void council_mma(const float* __restrict__ bias)
{
    extern __shared__ __half smem[];
    const int t = threadIdx.x, lane = t & 31, wid = t >> 5;
    const int wm = wid & 3, wn = wid >> 2;
    const int m0 = blockIdx.x * BM, n0 = blockIdx.y * BN, e = blockIdx.z;

    const size_t ldA = (MODE == 0) ? C_DIM : H_DIM;
    const size_t ldB = (MODE == 0) ? H_DIM : C_DIM;
    const int nstot = (int)(ldA / BK);   // 24 or 96

    const __half* Ag = (MODE == 0) ? (g_x16 + (size_t)m0 * C_DIM)
                                   : (g_h16 + ((size_t)e * N_TOK + m0) * H_DIM);
    const __half* Bg = (MODE == 0) ? (g_w1h + (size_t)e * C_DIM * H_DIM + n0)
                                   : (g_w2h + (size_t)e * H_DIM * C_DIM + n0);

    float acc[2][8][4];
#pragma unroll
    for (int mi = 0; mi < 2; mi++)
#pragma unroll
        for (int n8 = 0; n8 < 8; n8++)
#pragma unroll
            for (int q = 0; q < 4; q++) acc[mi][n8][q] = 0.0f;

    auto issue = [&](int s) {
        const int slot = s % NSTAGES;
        const uint32_t sA = smem_u32(smem + (size_t)slot * STAGE_ELTS);
        const uint32_t sB = sA + A_ELTS * 2;
        const int k0 = s * BK;
#pragma unroll
        for (int j = 0; j < 2; j++) {   // A: 128 rows x 4 chunks = 512 cp16 -> 2/thread
            int c = t + 256 * j;
            int r = c >> 2, kp = c & 3;
            cp16(sA + (r * ASTRIDE + kp * 8) * 2, Ag + (size_t)r * ldA + k0 + kp * 8);
        }
#pragma unroll
        for (int j = 0; j < 2; j++) {   // B: 32 rows x 16 chunks = 512 cp16 -> 2/thread
            int c = t + 256 * j;
            int rk = c >> 4, np = c & 15;
            cp16(sB + (rk * BSTRIDE + np * 8) * 2, Bg + (size_t)(k0 + rk) * ldB + np * 8);
        }
    };

    issue(0); CP_COMMIT;
    issue(1); CP_COMMIT;
    issue(2); CP_COMMIT;
    issue(3); CP_COMMIT;
    for (int s = 0; s < nstot; s++) {
        CP_WAIT3;
        __syncthreads();
        if (s + 4 < nstot) issue(s + 4);
        CP_COMMIT;
        const __half* st = smem + (size_t)(s % NSTAGES) * STAGE_ELTS;
        mma_stage(st, st + A_ELTS, lane, wm, wn, acc);
    }

    // ---- epilogue ----
    const int gid = lane >> 2, tg = lane & 3;
#pragma unroll
    for (int mi = 0; mi < 2; mi++) {
        int m = m0 + wm * 32 + mi * 16 + gid;
        if (MODE == 0) {
#pragma unroll
            for (int n8 = 0; n8 < 8; n8++) {
                int n = n0 + wn * 64 + n8 * 8 + tg * 2;
                float b0 = bias[e * H_DIM + n], b1v = bias[e * H_DIM + n + 1];
                float* a = acc[mi][n8];
                size_t gi = ((size_t)e * N_TOK + m) * H_DIM + n;
                __half2 v0 = __floats2half2_rn(gelu_f(a[0] + b0), gelu_f(a[1] + b1v));
                __half2 v1 = __floats2half2_rn(gelu_f(a[2] + b0), gelu_f(a[3] + b1v));
                *reinterpret_cast<__half2*>(&g_h16[gi]) = v0;
                *reinterpret_cast<__half2*>(&g_h16[gi + (size_t)8 * H_DIM]) = v1;
            }
        } else {
            float g0 = g_gates[m * E_NUM + e];
            float g1 = g_gates[(m + 8) * E_NUM + e];
#pragma unroll
            for (int n8 = 0; n8 < 8; n8++) {
                int n = n0 + wn * 64 + n8 * 8 + tg * 2;
                float* a = acc[mi][n8];
                size_t gi = (size_t)e * N_TOK * C_DIM + (size_t)m * C_DIM + n;
                *reinterpret_cast<float2*>(&g_part[gi]) = make_float2(a[0] * g0, a[1] * g0);
                *reinterpret_cast<float2*>(&g_part[gi + (size_t)8 * C_DIM]) =
                    make_float2(a[2] * g1, a[3] * g1);
            }
        }
    }
}

// ---------------- finalize ---------------------------------------------------
__global__ void finalize_kernel(const float* __restrict__ b2, float* __restrict__ out)
{
    int i4 = blockIdx.x * 256 + threadIdx.x;
    if (i4 >= N_TOK * C_DIM / 4) return;
    int i = i4 * 4, m = i / C_DIM, c = i % C_DIM;
    float4 s = make_float4(0.f, 0.f, 0.f, 0.f);
#pragma unroll 8
    for (int e = 0; e < E_NUM; e++) {
        float4 p = *(const float4*)&g_part[(size_t)e * N_TOK * C_DIM + i];
        float g = g_gates[m * E_NUM + e];
        const float* bb = &b2[e * C_DIM + c];
        s.x += p.x + g * bb[0]; s.y += p.y + g * bb[1];
        s.z += p.z + g * bb[2]; s.w += p.w + g * bb[3];
    }
    *(float4*)&out[i] = s;
}

// ---------------- launch -----------------------------------------------------
extern "C" void kernel_launch(void* const* d_in, const int* in_sizes, int n_in,
                              void* d_out, int out_size)
{
    (void)in_sizes; (void)n_in; (void)out_size;
    const float* x      = (const float*)d_in[0];
    const float* gate_w = (const float*)d_in[1];
    const float* gate_b = (const float*)d_in[2];
    const float* w1     = (const float*)d_in[3];
    const float* b1     = (const float*)d_in[4];
    const float* w2     = (const float*)d_in[5];
    const float* b2     = (const float*)d_in[6];
    float* out = (float*)d_out;

    static int attr_done = 0;
    if (!attr_done) {
        cudaFuncSetAttribute(council_mma<0>, cudaFuncAttributeMaxDynamicSharedMemorySize, SMEM_BYTES);
        cudaFuncSetAttribute(council_mma<1>, cudaFuncAttributeMaxDynamicSharedMemorySize, SMEM_BYTES);
        attr_done = 1;
    }

    __half *xh, *w1h, *w2h;
    cudaGetSymbolAddress((void**)&xh,  g_x16);
    cudaGetSymbolAddress((void**)&w1h, g_w1h);
    cudaGetSymbolAddress((void**)&w2h, g_w2h);

    const int n4x = N_TOK * C_DIM / 4;
    const int n4w = (int)((size_t)E_NUM * C_DIM * H_DIM / 4);

    gate_kernel<<<N_TOK / 8, 256>>>(x, gate_w, gate_b);
    convert_kernel<<<(n4x + 255) / 256, 256>>>((const float4*)x, (uint2*)xh, n4x);
    convert_kernel<<<(n4w + 255) / 256, 256>>>((const float4*)w1, (uint2*)w1h, n4w);
    convert_kernel<<<(n4w + 255) / 256, 256>>>((const float4*)w2, (uint2*)w2h, n4w);

    council_mma<0><<<dim3(N_TOK / BM, H_DIM / BN, E_NUM), 256, SMEM_BYTES>>>(b1);
    council_mma<1><<<dim3(N_TOK / BM, C_DIM / BN, E_NUM), 256, SMEM_BYTES>>>(nullptr);
    finalize_kernel<<<(N_TOK * C_DIM / 4 + 255) / 256, 256>>>(b2, out);
}